// round 4
// baseline (speedup 1.0000x reference)
#include <cuda_runtime.h>
#include <cuda_bf16.h>
#include <math.h>

#define BB 8
#define NN 96
#define DD 16
#define H0 50
#define H1 50
#define OUTD 64
#define SLOPE 0.05f
#define NI 8            // i's per block
#define NTH 384
#define NWARP 12

struct SmemT {
    float xb[NN*17];          // x rows, padded
    float W1s[51*H0];         // all of W1
    float W2s[83*H1];         // all of W2
    float W3s[66*OUTD];       // all of W3
    float Ps[NN*H0];          // P[j,h]
    float adjxS[NN*DD];       // (adj@x)[j,d]
    float disI[NI*NN];        // dis rows for block's i's
    float A_i[NI*H0];
    float tacc[NI*H0];
    float m2s[NI*H1];
    float sdikS[NI*NN];
    float degS[NN];
    float sdjkS[NN];
    float b1s[H0+2], b2s[H1+2], b3s[OUTD];
    int   nnzS[NN];
    unsigned char nzlist[NN*NN];
};

__device__ __forceinline__ float leaky(float v) { return v >= 0.f ? v : SLOPE * v; }

__global__ void __launch_bounds__(NTH) sgc_fused(
    const float* __restrict__ x, const float* __restrict__ adj,
    const float* __restrict__ W1, const float* __restrict__ b1,
    const float* __restrict__ W2, const float* __restrict__ b2,
    const float* __restrict__ W3, const float* __restrict__ b3,
    float* __restrict__ out)
{
    extern __shared__ unsigned char smem_raw[];
    SmemT& S = *(SmemT*)smem_raw;
    const int tid  = threadIdx.x;
    const int w    = tid >> 5, lane = tid & 31;
    const int b    = blockIdx.x / (NN/NI);
    const int i0   = (blockIdx.x % (NN/NI)) * NI;

    // ---- Phase 1: front-batched staging + adj compaction ----
    {
        const float4* xv = (const float4*)(x + b*NN*DD);
        {   // NN*DD/4 = 384 == NTH
            float4 v = xv[tid];
            const int base = (tid >> 2)*17 + (tid & 3)*4;
            S.xb[base] = v.x; S.xb[base+1] = v.y; S.xb[base+2] = v.z; S.xb[base+3] = v.w;
        }
        const float2* w1v = (const float2*)W1;
        #pragma unroll
        for (int idx = tid; idx < 51*H0/2; idx += NTH) ((float2*)S.W1s)[idx] = w1v[idx];
        const float2* w2v = (const float2*)W2;
        #pragma unroll
        for (int idx = tid; idx < 83*H1/2; idx += NTH) ((float2*)S.W2s)[idx] = w2v[idx];
        const float4* w3v = (const float4*)W3;
        #pragma unroll
        for (int idx = tid; idx < 66*OUTD/4; idx += NTH) ((float4*)S.W3s)[idx] = w3v[idx];
        if (tid < H0)                         S.b1s[tid]       = b1[tid];
        else if (tid >= 64  && tid < 64+H1)   S.b2s[tid-64]    = b2[tid-64];
        else if (tid >= 128 && tid < 128+OUTD)S.b3s[tid-128]   = b3[tid-128];

        // adj rows -> compacted neighbor lists (adj is exactly 0/1)
        for (int j = w; j < NN; j += NWARP) {
            const float* row = adj + (b*NN + j)*NN;
            const float a0 = row[lane], a1 = row[lane+32], a2 = row[lane+64];
            const unsigned m0 = __ballot_sync(~0u, a0 != 0.f);
            const unsigned m1 = __ballot_sync(~0u, a1 != 0.f);
            const unsigned m2 = __ballot_sync(~0u, a2 != 0.f);
            const int c0 = __popc(m0), c1 = __popc(m1), c2 = __popc(m2);
            const unsigned lt = (1u << lane) - 1u;
            unsigned char* nl = S.nzlist + j*NN;
            if (a0 != 0.f) nl[__popc(m0 & lt)]            = (unsigned char)lane;
            if (a1 != 0.f) nl[c0 + __popc(m1 & lt)]       = (unsigned char)(lane+32);
            if (a2 != 0.f) nl[c0 + c1 + __popc(m2 & lt)]  = (unsigned char)(lane+64);
            if (lane == 0) { S.nnzS[j] = c0+c1+c2; S.degS[j] = (float)(c0+c1+c2); }
        }
    }
    __syncthreads();

    // ---- Phase 2: disI rows, adjx (sparse), sd_jk (sparse) ----
    for (int idx = tid; idx < NI*NN; idx += NTH) {
        const int ii = idx / NN, k = idx % NN, i = i0 + ii;
        float d2 = 1e-10f;
        #pragma unroll
        for (int d = 0; d < DD; d++) { const float df = S.xb[i*17+d] - S.xb[k*17+d]; d2 += df*df; }
        S.disI[ii*NN + k] = sqrtf(d2);
    }
    for (int idx = tid; idx < NN*DD; idx += NTH) {
        const int j = idx / DD, d = idx % DD;
        const int nn = S.nnzS[j];
        const unsigned char* nl = S.nzlist + j*NN;
        float acc = 0.f;
        for (int m = 0; m < nn; m++) acc += S.xb[nl[m]*17 + d];
        S.adjxS[j*DD + d] = acc;
    }
    for (int j = w; j < NN; j += NWARP) {
        const int nn = S.nnzS[j];
        const unsigned char* nl = S.nzlist + j*NN;
        float acc = 0.f;
        for (int m = lane; m < nn; m += 32) {
            const int k = nl[m];
            float d2 = 1e-10f;
            #pragma unroll
            for (int d = 0; d < DD; d++) { const float df = S.xb[j*17+d] - S.xb[k*17+d]; d2 += df*df; }
            acc += sqrtf(d2);
        }
        #pragma unroll
        for (int o = 16; o; o >>= 1) acc += __shfl_down_sync(~0u, acc, o);
        if (lane == 0) S.sdjkS[j] = acc;
    }
    __syncthreads();

    // ---- Phase 3: P (h-paired for float2 weight loads), A_i, sd_ik ----
    for (int idx = tid; idx < NN*(H0/2); idx += NTH) {
        const int j = idx / (H0/2), hp = idx % (H0/2), h = 2*hp;
        float Bv0 = 0.f, Bv1 = 0.f, Cv0 = 0.f, Cv1 = 0.f;
        #pragma unroll
        for (int d = 0; d < DD; d++) {
            const float xv = S.xb[j*17 + d], av = S.adjxS[j*DD + d];
            const float2 wB = *(const float2*)&S.W1s[(DD   + d)*H0 + h];
            const float2 wC = *(const float2*)&S.W1s[(2*DD + d)*H0 + h];
            Bv0 = fmaf(xv, wB.x, Bv0); Bv1 = fmaf(xv, wB.y, Bv1);
            Cv0 = fmaf(av, wC.x, Cv0); Cv1 = fmaf(av, wC.y, Cv1);
        }
        const float dg = S.degS[j], sj = S.sdjkS[j];
        const float2 wjk = *(const float2*)&S.W1s[(3*DD + 1)*H0 + h];
        const float2 bb  = *(const float2*)&S.b1s[h];
        S.Ps[j*H0 + h]     = dg*(Bv0 + bb.x) + Cv0 + sj*wjk.x;
        S.Ps[j*H0 + h + 1] = dg*(Bv1 + bb.y) + Cv1 + sj*wjk.y;
    }
    for (int idx = tid; idx < NI*H0; idx += NTH) {
        const int ii = idx / H0, h = idx % H0, i = i0 + ii;
        float acc = 0.f;
        #pragma unroll
        for (int d = 0; d < DD; d++) acc = fmaf(S.xb[i*17+d], S.W1s[d*H0 + h], acc);
        S.A_i[ii*H0 + h] = acc;
    }
    for (int idx = tid; idx < NI*NN; idx += NTH) {
        const int ii = idx / NN, m = idx % NN, i = i0 + ii;
        if (m < S.nnzS[i]) {
            const int j = S.nzlist[i*NN + m];
            const int nnj = S.nnzS[j];
            const unsigned char* nl = S.nzlist + j*NN;
            float acc = 0.f;
            for (int m2 = 0; m2 < nnj; m2++) acc += S.disI[ii*NN + nl[m2]];
            S.sdikS[ii*NN + m] = acc;
        }
    }
    __syncthreads();

    // ---- Phase 4: t[i,h] = sum over nz(i) of leaky(S) ----
    for (int idx = tid; idx < NI*H0; idx += NTH) {
        const int ii = idx / H0, h = idx % H0, i = i0 + ii;
        const float wij = S.W1s[(3*DD)*H0 + h];
        const float wik = S.W1s[(3*DD + 2)*H0 + h];
        const float Ah  = S.A_i[ii*H0 + h];
        const int nn = S.nnzS[i];
        float acc = 0.f;
        for (int m = 0; m < nn; m++) {
            const int j = S.nzlist[i*NN + m];
            const float dg = S.degS[j];
            const float Sv = fmaf(dg, Ah,
                             fmaf(dg * S.disI[ii*NN + j], wij,
                             fmaf(S.sdikS[ii*NN + m], wik, S.Ps[j*H0 + h])));
            acc += leaky(Sv);
        }
        S.tacc[ii*H0 + h] = acc;
    }
    __syncthreads();

    // ---- Phase 5: m2_sum ----
    for (int idx = tid; idx < NI*H1; idx += NTH) {
        const int ii = idx / H1, h1 = idx % H1, i = i0 + ii;
        const float dg = S.degS[i];
        float acc = dg * S.b2s[h1];
        #pragma unroll
        for (int d = 0; d < DD; d++) {
            acc = fmaf(dg * S.xb[i*17+d],  S.W2s[d*H1 + h1], acc);
            acc = fmaf(S.adjxS[i*DD + d],  S.W2s[(DD + d)*H1 + h1], acc);
        }
        acc = fmaf(S.sdjkS[i], S.W2s[(2*DD)*H1 + h1], acc);
        #pragma unroll 10
        for (int h = 0; h < H0; h++)
            acc = fmaf(S.tacc[ii*H0 + h], S.W2s[(2*DD + 1 + h)*H1 + h1], acc);
        S.m2s[ii*H1 + h1] = leaky(acc);
    }
    __syncthreads();

    // ---- Phase 6: output ----
    for (int idx = tid; idx < NI*OUTD; idx += NTH) {
        const int ii = idx / OUTD, o = idx % OUTD, i = i0 + ii;
        float acc = S.b3s[o];
        #pragma unroll
        for (int d = 0; d < DD; d++) acc = fmaf(S.xb[i*17+d], S.W3s[d*OUTD + o], acc);
        #pragma unroll 10
        for (int h = 0; h < H1; h++) acc = fmaf(S.m2s[ii*H1 + h], S.W3s[(DD + h)*OUTD + o], acc);
        out[(b*NN + i)*OUTD + o] = leaky(acc);
    }
}

extern "C" void kernel_launch(void* const* d_in, const int* in_sizes, int n_in,
                              void* d_out, int out_size)
{
    const float* x   = (const float*)d_in[0];
    const float* adj = (const float*)d_in[1];
    const float* W1  = (const float*)d_in[2];
    const float* b1  = (const float*)d_in[3];
    const float* W2  = (const float*)d_in[4];
    const float* b2  = (const float*)d_in[5];
    const float* W3  = (const float*)d_in[6];
    const float* b3  = (const float*)d_in[7];
    float* out = (float*)d_out;

    static bool attr_done = false;
    if (!attr_done) {
        cudaFuncSetAttribute(sgc_fused,
            cudaFuncAttributeMaxDynamicSharedMemorySize, (int)sizeof(SmemT));
        attr_done = true;
    }
    sgc_fused<<<BB*(NN/NI), NTH, sizeof(SmemT)>>>(x, adj, W1, b1, W2, b2, W3, b3, out);
}